// round 1
// baseline (speedup 1.0000x reference)
#include <cuda_runtime.h>
#include <cstdint>

// Problem constants (fixed shapes from reference)
#define CIN   2112
#define COUT  192
#define HW    49
#define BATCH 256
#define M_TOTAL (BATCH * HW)   // 12544
#define EPS_BN 1e-5f

// GEMM tiling
#define BM 64
#define BN 192
#define BK 16
#define KTILES (CIN / BK)      // 132

// Precomputed BN affine: scale[c] = gamma*rsqrt(var+eps), shift[c] = beta - mean*scale
__device__ float g_scale[CIN];
__device__ float g_shift[CIN];

__global__ void prep_kernel(const float* __restrict__ gamma,
                            const float* __restrict__ beta,
                            const float* __restrict__ mean,
                            const float* __restrict__ var) {
    int c = blockIdx.x * blockDim.x + threadIdx.x;
    if (c < CIN) {
        float inv = rsqrtf(var[c] + EPS_BN);
        float s = gamma[c] * inv;
        g_scale[c] = s;
        g_shift[c] = beta[c] - mean[c] * s;
    }
}

__device__ __forceinline__ uint32_t f2tf(float f) {
    uint32_t u;
    asm("cvt.rna.tf32.f32 %0, %1;" : "=r"(u) : "f"(f));
    return u;
}

// C[M, N] = relu(x*scale+shift)[M, K] * W[N, K]^T
// x layout: [b][k][hw], m = b*49 + hw  (A element A[m,k] = x[b, k, hw])
// out layout: [b][n][hw]
__global__ __launch_bounds__(256, 2)
void gemm_kernel(const float* __restrict__ x,
                 const float* __restrict__ W,
                 float* __restrict__ out) {
    // [k][m] / [k][n]; strides 72 / 200 -> fragment LDS bank = (8k + idx) % 32 (conflict-free)
    __shared__ uint32_t As[2][BK][BM + 8];
    __shared__ uint32_t Bs[2][BK][BN + 8];

    const int tid  = threadIdx.x;
    const int lane = tid & 31;
    const int warp = tid >> 5;
    const int wm = warp & 1;        // 2 M-warps (32 rows each)
    const int wn = warp >> 1;       // 4 N-warps (48 cols each)
    const int g  = lane >> 2;       // 0..7
    const int tq = lane & 3;        // 0..3

    const int m_base = blockIdx.x * BM;

    // ---- A global-load mapping: 64 m x 16 k per tile; thread -> (m, 4 k's) ----
    const int am  = tid & 63;           // m within tile (coalesced, lanes contiguous)
    const int aks = tid >> 6;           // k sub-slot 0..3
    const int m_glob = m_base + am;
    const int ab  = m_glob / HW;
    const int ahw = m_glob % HW;
    const float* xrow = x + (size_t)ab * CIN * HW + ahw;  // +49 per k

    // ---- B global-load mapping: 16 k x 192 n per tile; thread -> (k, 12 n's) ----
    const int bk  = tid & 15;
    const int bn0 = tid >> 4;           // 0..15

    float acc[2][6][4];
    #pragma unroll
    for (int i = 0; i < 2; i++)
        #pragma unroll
        for (int j = 0; j < 6; j++)
            #pragma unroll
            for (int c = 0; c < 4; c++) acc[i][j][c] = 0.f;

    float a_reg[4];
    float b_reg[12];

    // ---- prologue: fill stage 0 ----
    {
        #pragma unroll
        for (int i = 0; i < 4; i++) {
            int kl = aks + i * 4;
            float v = fmaf(xrow[(size_t)kl * HW], g_scale[kl], g_shift[kl]);
            As[0][kl][am] = f2tf(fmaxf(v, 0.f));
        }
        #pragma unroll
        for (int i = 0; i < 12; i++) {
            int n = bn0 + i * 16;
            Bs[0][bk][n] = f2tf(W[(size_t)n * CIN + bk]);
        }
    }
    __syncthreads();

    // ---- main loop: register-prefetch + smem double buffer ----
    for (int t = 0; t < KTILES; t++) {
        const int cur = t & 1;
        const int nxt = cur ^ 1;

        if (t + 1 < KTILES) {
            const int k0 = (t + 1) * BK;
            #pragma unroll
            for (int i = 0; i < 4; i++) {
                int k = k0 + aks + i * 4;
                a_reg[i] = xrow[(size_t)k * HW];
            }
            #pragma unroll
            for (int i = 0; i < 12; i++) {
                int n = bn0 + i * 16;
                b_reg[i] = W[(size_t)n * CIN + k0 + bk];
            }
        }

        // compute 2 k-steps of 8 from stage cur
        #pragma unroll
        for (int s = 0; s < 2; s++) {
            uint32_t af[2][4], bf[6][2];
            #pragma unroll
            for (int i = 0; i < 2; i++) {
                int mb = wm * 32 + i * 16 + g;
                af[i][0] = As[cur][s * 8 + tq    ][mb];
                af[i][1] = As[cur][s * 8 + tq    ][mb + 8];
                af[i][2] = As[cur][s * 8 + tq + 4][mb];
                af[i][3] = As[cur][s * 8 + tq + 4][mb + 8];
            }
            #pragma unroll
            for (int j = 0; j < 6; j++) {
                int nb = wn * 48 + j * 8 + g;
                bf[j][0] = Bs[cur][s * 8 + tq    ][nb];
                bf[j][1] = Bs[cur][s * 8 + tq + 4][nb];
            }
            #pragma unroll
            for (int i = 0; i < 2; i++)
                #pragma unroll
                for (int j = 0; j < 6; j++) {
                    asm volatile(
                        "mma.sync.aligned.m16n8k8.row.col.f32.tf32.tf32.f32 "
                        "{%0,%1,%2,%3}, {%4,%5,%6,%7}, {%8,%9}, {%0,%1,%2,%3};\n"
                        : "+f"(acc[i][j][0]), "+f"(acc[i][j][1]),
                          "+f"(acc[i][j][2]), "+f"(acc[i][j][3])
                        : "r"(af[i][0]), "r"(af[i][1]), "r"(af[i][2]), "r"(af[i][3]),
                          "r"(bf[j][0]), "r"(bf[j][1]));
                }
        }

        if (t + 1 < KTILES) {
            const int k0 = (t + 1) * BK;
            #pragma unroll
            for (int i = 0; i < 4; i++) {
                int kl = aks + i * 4;
                int k  = k0 + kl;
                float v = fmaf(a_reg[i], g_scale[k], g_shift[k]);
                As[nxt][kl][am] = f2tf(fmaxf(v, 0.f));
            }
            #pragma unroll
            for (int i = 0; i < 12; i++) {
                Bs[nxt][bk][bn0 + i * 16] = f2tf(b_reg[i]);
            }
        }
        __syncthreads();
    }

    // ---- epilogue: scatter to out[b][n][hw] ----
    #pragma unroll
    for (int i = 0; i < 2; i++) {
        #pragma unroll
        for (int half = 0; half < 2; half++) {
            int m  = m_base + wm * 32 + i * 16 + g + half * 8;
            int b  = m / HW;
            int hw = m % HW;
            float* orow = out + (size_t)b * COUT * HW + hw;
            #pragma unroll
            for (int j = 0; j < 6; j++) {
                int n0 = wn * 48 + j * 8 + 2 * tq;
                orow[(size_t)n0 * HW]       = acc[i][j][half * 2 + 0];
                orow[(size_t)(n0 + 1) * HW] = acc[i][j][half * 2 + 1];
            }
        }
    }
}

extern "C" void kernel_launch(void* const* d_in, const int* in_sizes, int n_in,
                              void* d_out, int out_size) {
    const float* x     = (const float*)d_in[0];
    const float* gamma = (const float*)d_in[1];
    const float* beta  = (const float*)d_in[2];
    const float* mean  = (const float*)d_in[3];
    const float* var   = (const float*)d_in[4];
    const float* W     = (const float*)d_in[5];
    float* out = (float*)d_out;

    prep_kernel<<<(CIN + 255) / 256, 256>>>(gamma, beta, mean, var);
    gemm_kernel<<<M_TOTAL / BM, 256>>>(x, W, out);
}

// round 3
// speedup vs baseline: 1.9636x; 1.9636x over previous
#include <cuda_runtime.h>
#include <cuda_fp16.h>
#include <cstdint>

// ---------------- problem constants ----------------
#define CIN     2112
#define COUT    192
#define HW      49
#define M_TOTAL 12544          // 256*49
#define BM      64
#define BN      96
#define BK      32
#define CHUNKS  66             // 2112/32
#define NTH     256
#define EPS_BN  1e-5f
#define AST     40             // halfs per A smem row (32 data + 8 pad = 80B)
#define BST     40             // halfs per B smem row

// ---------------- persistent scratch (no allocs allowed) ----------------
__device__ float2 g_bn[CIN];              // {scale, shift}
__device__ __half g_wh[COUT * CIN];       // W pre-converted to fp16

__global__ void prep_bn_k(const float* __restrict__ gamma, const float* __restrict__ beta,
                          const float* __restrict__ mean, const float* __restrict__ var) {
    int c = blockIdx.x * blockDim.x + threadIdx.x;
    if (c < CIN) {
        float inv = rsqrtf(var[c] + EPS_BN);
        float s = gamma[c] * inv;
        g_bn[c] = make_float2(s, fmaf(-mean[c], s, beta[c]));
    }
}

__global__ void prep_w_k(const float* __restrict__ W) {
    int i = blockIdx.x * blockDim.x + threadIdx.x;
    if (i < COUT * CIN) g_wh[i] = __float2half_rn(W[i]);
}

// ---------------- helpers ----------------
__device__ __forceinline__ uint32_t smem_u32(const void* p) {
    uint32_t a;
    asm("{ .reg .u64 t; cvta.to.shared.u64 t, %1; cvt.u32.u64 %0, t; }" : "=r"(a) : "l"(p));
    return a;
}
__device__ __forceinline__ void cp16(uint32_t dst, const void* src) {
    asm volatile("cp.async.cg.shared.global [%0], [%1], 16;" :: "r"(dst), "l"(src));
}

// ---------------- fused BN+ReLU + fp16 GEMM ----------------
// C[M=12544, N=192] = relu(x*s+t)[M, K=2112] * W[N, K]^T
// grid: 392 CTAs = 196 m-tiles x 2 n-tiles (paired bids share x via L2)
__global__ __launch_bounds__(NTH, 3)
void gemm_k(const float* __restrict__ x, float* __restrict__ out) {
    __shared__ float2 bns[CIN];                         // 16896 B
    __shared__ __align__(16) __half As[2][BM * AST];    // 2 x 5120 B
    __shared__ __align__(16) __half Bs[2][BN * BST];    // 2 x 7680 B

    const int tid  = threadIdx.x;
    const int lane = tid & 31, warp = tid >> 5;
    const int wm = warp & 1, wn = warp >> 1;            // 2 x 4 warp grid
    const int g  = lane >> 2, tq = lane & 3;

    const int m0 = (blockIdx.x >> 1) * BM;
    const int n0 = (blockIdx.x & 1) * BN;

    for (int c = tid; c < CIN; c += NTH) bns[c] = g_bn[c];

    // A loader mapping: thread -> (m = tid&63, 8 consecutive k at kq*8)
    const int am = tid & 63, kq = tid >> 6;
    const int mg = m0 + am;
    const float* xp = x + (size_t)(mg / HW) * ((size_t)CIN * HW) + (mg % HW)
                        + (size_t)(kq * 8) * HW;

    const uint32_t sB = smem_u32(&Bs[0][0]);
    const __half* wsrc0 = g_wh + (size_t)n0 * CIN;

    float acc[2][3][4] = {};
    float ar[8];

    // ---- prologue: chunk 0 ----
    #pragma unroll
    for (int j = 0; j < 8; j++) ar[j] = __ldg(xp + (size_t)j * HW);
    {
        int idx = tid, n = idx >> 2, kb = idx & 3;
        cp16(sB + n * 80 + kb * 16, wsrc0 + (size_t)n * CIN + kb * 8);
        if (tid < 128) {
            idx = tid + 256; n = idx >> 2; kb = idx & 3;
            cp16(sB + n * 80 + kb * 16, wsrc0 + (size_t)n * CIN + kb * 8);
        }
        asm volatile("cp.async.commit_group;");
    }
    __syncthreads();                                    // bns table ready
    {
        const int k0 = kq * 8;
        __half h[8];
        #pragma unroll
        for (int j = 0; j < 8; j++) {
            float2 s = bns[k0 + j];
            h[j] = __float2half_rn(fmaxf(fmaf(ar[j], s.x, s.y), 0.f));
        }
        *(uint4*)&As[0][am * AST + kq * 8] = *(uint4*)h;
    }
    asm volatile("cp.async.wait_group 0;");
    __syncthreads();

    // ---- main loop ----
    #pragma unroll 1
    for (int t = 0; t < CHUNKS; t++) {
        const int cur = t & 1, nxt = cur ^ 1;

        if (t + 1 < CHUNKS) {
            const float* xp2 = xp + (size_t)(t + 1) * BK * HW;
            #pragma unroll
            for (int j = 0; j < 8; j++) ar[j] = __ldg(xp2 + (size_t)j * HW);
            const __half* ws = wsrc0 + (size_t)(t + 1) * BK;
            const uint32_t bb = sB + nxt * (BN * BST * 2);
            int idx = tid, n = idx >> 2, kb = idx & 3;
            cp16(bb + n * 80 + kb * 16, ws + (size_t)n * CIN + kb * 8);
            if (tid < 128) {
                idx = tid + 256; n = idx >> 2; kb = idx & 3;
                cp16(bb + n * 80 + kb * 16, ws + (size_t)n * CIN + kb * 8);
            }
            asm volatile("cp.async.commit_group;");
        }

        // compute chunk `cur`: 2 k16 steps x (2 m-tiles x 3 n-tiles)
        #pragma unroll
        for (int s = 0; s < 2; s++) {
            uint32_t a[2][4], b[3][2];
            #pragma unroll
            for (int mi = 0; mi < 2; mi++) {
                const int r = wm * 32 + mi * 16 + g;
                const __half* base = &As[cur][r * AST + s * 16 + tq * 2];
                a[mi][0] = *(const uint32_t*)(base);
                a[mi][1] = *(const uint32_t*)(base + 8 * AST);
                a[mi][2] = *(const uint32_t*)(base + 8);
                a[mi][3] = *(const uint32_t*)(base + 8 * AST + 8);
            }
            #pragma unroll
            for (int ni = 0; ni < 3; ni++) {
                const int r = wn * 24 + ni * 8 + g;
                const __half* base = &Bs[cur][r * BST + s * 16 + tq * 2];
                b[ni][0] = *(const uint32_t*)(base);
                b[ni][1] = *(const uint32_t*)(base + 8);
            }
            #pragma unroll
            for (int mi = 0; mi < 2; mi++)
                #pragma unroll
                for (int ni = 0; ni < 3; ni++) {
                    asm volatile(
                        "mma.sync.aligned.m16n8k16.row.col.f32.f16.f16.f32 "
                        "{%0,%1,%2,%3},{%4,%5,%6,%7},{%8,%9},{%0,%1,%2,%3};"
                        : "+f"(acc[mi][ni][0]), "+f"(acc[mi][ni][1]),
                          "+f"(acc[mi][ni][2]), "+f"(acc[mi][ni][3])
                        : "r"(a[mi][0]), "r"(a[mi][1]), "r"(a[mi][2]), "r"(a[mi][3]),
                          "r"(b[ni][0]), "r"(b[ni][1]));
                }
        }

        if (t + 1 < CHUNKS) {
            const int k0 = (t + 1) * BK + kq * 8;
            __half h[8];
            #pragma unroll
            for (int j = 0; j < 8; j++) {
                float2 s = bns[k0 + j];
                h[j] = __float2half_rn(fmaxf(fmaf(ar[j], s.x, s.y), 0.f));
            }
            *(uint4*)&As[nxt][am * AST + kq * 8] = *(uint4*)h;
            asm volatile("cp.async.wait_group 0;");
        }
        __syncthreads();
    }

    // ---- epilogue: out[b][n][hw] ----
    #pragma unroll
    for (int mi = 0; mi < 2; mi++) {
        #pragma unroll
        for (int hh = 0; hh < 2; hh++) {
            const int m = m0 + wm * 32 + mi * 16 + g + hh * 8;
            float* ob = out + (size_t)(m / HW) * ((size_t)COUT * HW) + (m % HW);
            #pragma unroll
            for (int ni = 0; ni < 3; ni++) {
                const int cc = n0 + wn * 24 + ni * 8 + tq * 2;
                ob[(size_t)cc * HW]       = acc[mi][ni][hh * 2 + 0];
                ob[(size_t)(cc + 1) * HW] = acc[mi][ni][hh * 2 + 1];
            }
        }
    }
}

extern "C" void kernel_launch(void* const* d_in, const int* in_sizes, int n_in,
                              void* d_out, int out_size) {
    const float* x     = (const float*)d_in[0];
    const float* gamma = (const float*)d_in[1];
    const float* beta  = (const float*)d_in[2];
    const float* mean  = (const float*)d_in[3];
    const float* var   = (const float*)d_in[4];
    const float* W     = (const float*)d_in[5];
    float* out = (float*)d_out;

    prep_bn_k<<<(CIN + 255) / 256, 256>>>(gamma, beta, mean, var);
    prep_w_k<<<(COUT * CIN + 255) / 256, 256>>>(W);
    gemm_k<<<(M_TOTAL / BM) * 2, NTH>>>(x, out);
}

// round 4
// speedup vs baseline: 2.2077x; 1.1243x over previous
#include <cuda_runtime.h>
#include <cuda_fp16.h>
#include <cstdint>

// ---------------- problem constants ----------------
#define CIN     2112
#define COUT    192
#define HW      49
#define M_TOTAL 12544          // 256*49
#define BM      64
#define BN      96
#define BK      32
#define CHUNKS  66             // 2112/32
#define NTH     256
#define EPS_BN  1e-5f
#define AST     40             // halfs per A smem row (80B)
#define BST     40             // halfs per B smem row (80B)
#define A_STAGE (BM * AST * 2) // 5120 B
#define B_STAGE (BN * BST * 2) // 7680 B

// ---------------- persistent scratch ----------------
__device__ __half g_wh[COUT * CIN];       // W pre-converted to fp16

__global__ void prep_w_k(const float* __restrict__ W) {
    int i = blockIdx.x * blockDim.x + threadIdx.x;
    if (i < COUT * CIN) g_wh[i] = __float2half_rn(W[i]);
}

// ---------------- helpers ----------------
__device__ __forceinline__ uint32_t smem_u32(const void* p) {
    uint32_t a;
    asm("{ .reg .u64 t; cvta.to.shared.u64 t, %1; cvt.u32.u64 %0, t; }" : "=r"(a) : "l"(p));
    return a;
}
__device__ __forceinline__ void cp16(uint32_t dst, const void* src) {
    asm volatile("cp.async.cg.shared.global [%0], [%1], 16;" :: "r"(dst), "l"(src));
}
__device__ __forceinline__ void ldm_x4(uint32_t* r, uint32_t addr) {
    asm volatile("ldmatrix.sync.aligned.m8n8.x4.shared.b16 {%0,%1,%2,%3}, [%4];"
                 : "=r"(r[0]), "=r"(r[1]), "=r"(r[2]), "=r"(r[3]) : "r"(addr));
}
__device__ __forceinline__ void ldm_x2(uint32_t* r, uint32_t addr) {
    asm volatile("ldmatrix.sync.aligned.m8n8.x2.shared.b16 {%0,%1}, [%2];"
                 : "=r"(r[0]), "=r"(r[1]) : "r"(addr));
}

// ---------------- fused BN+ReLU + fp16 GEMM ----------------
// C[M=12544, N=192] = relu(x*s+t)[M, K=2112] * W[N, K]^T
// grid: 392 CTAs = 196 m-tiles x 2 n-halves (paired bids share x via L2)
__global__ __launch_bounds__(NTH, 3)
void gemm_k(const float* __restrict__ x,
            const float* __restrict__ gamma, const float* __restrict__ beta,
            const float* __restrict__ mean,  const float* __restrict__ var,
            float* __restrict__ out) {
    __shared__ float2 bns[CIN];                         // 16896 B
    __shared__ __align__(16) __half As[2][BM * AST];    // 10240 B
    __shared__ __align__(16) __half Bs[2][BN * BST];    // 15360 B

    const int tid  = threadIdx.x;
    const int lane = tid & 31, warp = tid >> 5;
    const int wm = warp & 1, wn = warp >> 1;            // 2 x 4 warp grid
    const int g  = lane >> 2, tq = lane & 3;

    const int m0 = (blockIdx.x >> 1) * BM;
    const int n0 = (blockIdx.x & 1) * BN;

    // A loader mapping: thread -> (m = tid&63, 8 consecutive k at kq*8)
    const int am = tid & 63, kq = tid >> 6;
    const int mg = m0 + am;
    const float* xp = x + (size_t)(mg / HW) * ((size_t)CIN * HW) + (mg % HW)
                        + (size_t)(kq * 8) * HW;

    const uint32_t sA = smem_u32(&As[0][0]);
    const uint32_t sB = smem_u32(&Bs[0][0]);
    const __half* wsrc0 = g_wh + (size_t)n0 * CIN;

    // ldmatrix per-thread address components (byte offsets within a stage)
    const uint32_t offA = (uint32_t)(lane & 15) * 80u + (uint32_t)(lane >> 4) * 16u
                        + (uint32_t)(wm * 32) * 80u;
    const uint32_t offB01 = (uint32_t)(wn * 24 + ((lane >> 4) << 3) + (lane & 7)) * 80u
                          + (uint32_t)((lane >> 3) & 1) * 16u;
    const int l15 = lane & 15;
    const uint32_t offB2 = (uint32_t)(wn * 24 + 16 + (l15 & 7)) * 80u
                         + (uint32_t)(l15 >> 3) * 16u;

    float acc[2][3][4] = {};
    float ar[8];

    // ---- prologue ----
    #pragma unroll
    for (int j = 0; j < 8; j++) ar[j] = __ldg(xp + (size_t)j * HW);
    {
        int n = tid >> 2, kb = tid & 3;
        cp16(sB + n * 80 + kb * 16, wsrc0 + (size_t)n * CIN + kb * 8);
        if (tid < 128) {
            int idx = tid + 256; n = idx >> 2; kb = idx & 3;
            cp16(sB + n * 80 + kb * 16, wsrc0 + (size_t)n * CIN + kb * 8);
        }
        asm volatile("cp.async.commit_group;");
    }
    // BN affine table (fused: no separate prep launch)
    for (int c = tid; c < CIN; c += NTH) {
        float inv = rsqrtf(var[c] + EPS_BN);
        float s = gamma[c] * inv;
        bns[c] = make_float2(s, fmaf(-mean[c], s, beta[c]));
    }
    __syncthreads();                                    // bns visible
    {
        const int k0 = kq * 8;
        __half h[8];
        #pragma unroll
        for (int j = 0; j < 8; j++) {
            float2 s = bns[k0 + j];
            h[j] = __float2half_rn(fmaxf(fmaf(ar[j], s.x, s.y), 0.f));
        }
        *(uint4*)&As[0][am * AST + kq * 8] = *(uint4*)h;
    }
    asm volatile("cp.async.wait_group 0;");
    __syncthreads();

    // ---- main loop ----
    #pragma unroll 1
    for (int t = 0; t < CHUNKS; t++) {
        const int cur = t & 1, nxt = cur ^ 1;

        if (t + 1 < CHUNKS) {
            const float* xp2 = xp + (size_t)(t + 1) * BK * HW;
            #pragma unroll
            for (int j = 0; j < 8; j++) ar[j] = __ldg(xp2 + (size_t)j * HW);
            const __half* ws = wsrc0 + (size_t)(t + 1) * BK;
            const uint32_t bb = sB + nxt * B_STAGE;
            int n = tid >> 2, kb = tid & 3;
            cp16(bb + n * 80 + kb * 16, ws + (size_t)n * CIN + kb * 8);
            if (tid < 128) {
                int idx = tid + 256; n = idx >> 2; kb = idx & 3;
                cp16(bb + n * 80 + kb * 16, ws + (size_t)n * CIN + kb * 8);
            }
            asm volatile("cp.async.commit_group;");
        }

        // compute chunk `cur`: 2 k16 steps
        const uint32_t aBase = sA + cur * A_STAGE;
        const uint32_t bBase = sB + cur * B_STAGE;
        #pragma unroll
        for (int s = 0; s < 2; s++) {
            uint32_t a[2][4], b01[4], b2[2];
            ldm_x4(a[0], aBase + offA + s * 32);
            ldm_x4(a[1], aBase + offA + 16 * 80 + s * 32);
            ldm_x4(b01, bBase + offB01 + s * 32);
            ldm_x2(b2,  bBase + offB2  + s * 32);
            const uint32_t* bf[3] = { &b01[0], &b01[2], &b2[0] };
            #pragma unroll
            for (int mi = 0; mi < 2; mi++)
                #pragma unroll
                for (int ni = 0; ni < 3; ni++) {
                    asm volatile(
                        "mma.sync.aligned.m16n8k16.row.col.f32.f16.f16.f32 "
                        "{%0,%1,%2,%3},{%4,%5,%6,%7},{%8,%9},{%0,%1,%2,%3};"
                        : "+f"(acc[mi][ni][0]), "+f"(acc[mi][ni][1]),
                          "+f"(acc[mi][ni][2]), "+f"(acc[mi][ni][3])
                        : "r"(a[mi][0]), "r"(a[mi][1]), "r"(a[mi][2]), "r"(a[mi][3]),
                          "r"(bf[ni][0]), "r"(bf[ni][1]));
                }
        }

        if (t + 1 < CHUNKS) {
            const int k0 = (t + 1) * BK + kq * 8;
            __half h[8];
            #pragma unroll
            for (int j = 0; j < 8; j++) {
                float2 s = bns[k0 + j];
                h[j] = __float2half_rn(fmaxf(fmaf(ar[j], s.x, s.y), 0.f));
            }
            *(uint4*)&As[nxt][am * AST + kq * 8] = *(uint4*)h;
            asm volatile("cp.async.wait_group 0;");
        }
        __syncthreads();
    }

    // ---- epilogue: out[b][n][hw] ----
    #pragma unroll
    for (int mi = 0; mi < 2; mi++) {
        #pragma unroll
        for (int hh = 0; hh < 2; hh++) {
            const int m = m0 + wm * 32 + mi * 16 + g + hh * 8;
            float* ob = out + (size_t)(m / HW) * ((size_t)COUT * HW) + (m % HW);
            #pragma unroll
            for (int ni = 0; ni < 3; ni++) {
                const int cc = n0 + wn * 24 + ni * 8 + tq * 2;
                ob[(size_t)cc * HW]       = acc[mi][ni][hh * 2 + 0];
                ob[(size_t)(cc + 1) * HW] = acc[mi][ni][hh * 2 + 1];
            }
        }
    }
}

extern "C" void kernel_launch(void* const* d_in, const int* in_sizes, int n_in,
                              void* d_out, int out_size) {
    const float* x     = (const float*)d_in[0];
    const float* gamma = (const float*)d_in[1];
    const float* beta  = (const float*)d_in[2];
    const float* mean  = (const float*)d_in[3];
    const float* var   = (const float*)d_in[4];
    const float* W     = (const float*)d_in[5];
    float* out = (float*)d_out;

    prep_w_k<<<(COUT * CIN + 255) / 256, 256>>>(W);
    gemm_k<<<(M_TOTAL / BM) * 2, NTH>>>(x, gamma, beta, mean, var, out);
}